// round 10
// baseline (speedup 1.0000x reference)
#include <cuda_runtime.h>
#include <math.h>

// HyperbolicMLR fused. f32x2 pair spans (p,a): one FFMA2 feeds BOTH GEMMs.
// x tile stored as duplicated pairs (x,x); class tile as interleaved (p,a).
// Block 64b x 64c, thread 4b x 4c, 256 thr, 3 blocks/SM.

#define K_CURV 0.1f
#define SQRT_K 0.31622776601683794f
#define DDIM   64

typedef unsigned long long ull;

// dynamic smem (floats): xs 64*128, pa 64*128, scalars
#define SMF_XS   0                    // x dup pairs: row b, 32 chunks of (x,x,x',x')
#define SMF_PA   8192                 // class pairs: row c, 32 chunks of (p,a,p',a')
#define SMF_X2   16384                // |p_poin|^2      [64]
#define SMF_PAC  16448                // dot(mp,a_poin)  [64]
#define SMF_SC   16512                // scale           [64]
#define SMF_CF   16576                // 2*sqrt_k/a_norm [64]
#define SMF_Y2   16640                // |x_b|^2         [64]
#define SM_TOTAL ((16704) * 4)

__device__ __forceinline__ float2 unpack2(ull v) {
    float2 r;
    asm("mov.b64 {%0, %1}, %2;" : "=f"(r.x), "=f"(r.y) : "l"(v));
    return r;
}
__device__ __forceinline__ void ffma2(ull& acc, ull a, ull b) {
    asm("fma.rn.f32x2 %0, %1, %2, %0;" : "+l"(acc) : "l"(a), "l"(b));
}
__device__ __forceinline__ float rcp_a(float x)  { float r; asm("rcp.approx.f32 %0, %1;"  : "=f"(r) : "f"(x)); return r; }
__device__ __forceinline__ float sqrt_a(float x) { float r; asm("sqrt.approx.f32 %0, %1;" : "=f"(r) : "f"(x)); return r; }
__device__ __forceinline__ float lg2_a(float x)  { float r; asm("lg2.approx.f32 %0, %1;"  : "=f"(r) : "f"(x)); return r; }

__global__ void __launch_bounds__(256, 3)
hmlr_fused(const float* __restrict__ x,
           const float* __restrict__ a_vals,
           const float* __restrict__ p_vals,
           float* __restrict__ out, int B, int C) {
    extern __shared__ __align__(16) float sm[];
    float* xs   = sm + SMF_XS;
    float* pa   = sm + SMF_PA;
    float* s_x2 = sm + SMF_X2;
    float* s_pa = sm + SMF_PAC;
    float* s_sc = sm + SMF_SC;
    float* s_cf = sm + SMF_CF;
    float* s_y2 = sm + SMF_Y2;

    const int tid   = threadIdx.x;
    const int cBase = blockIdx.x * 64;
    const int bBase = blockIdx.y * 64;

    // ========== phase 1a: x tile fill (duplicate pairs, chunk-XOR swizzle) + y2 ==
    {
        const float4* Xv = (const float4*)(x + (size_t)bBase * DDIM);
#pragma unroll
        for (int it = 0; it < 4; ++it) {
            int lin = tid + it * 256;            // 0..1023 = row*16 + ch4
            float4 v = Xv[lin];
            int row = lin >> 4;                  // b row 0..63
            int ch4 = lin & 15;                  // input float4 idx -> d0 = 4*ch4
            int s   = (row >> 2) & 15;           // row-seeded chunk swizzle
            float* base = xs + row * 128;
            int m0 = (2 * ch4)     ^ s;          // chunk holds d = 2m, 2m+1
            int m1 = (2 * ch4 + 1) ^ s;
            *(float4*)(base + m0 * 4) = make_float4(v.x, v.x, v.y, v.y);
            *(float4*)(base + m1 * 4) = make_float4(v.z, v.z, v.w, v.w);
            float sres = v.x * v.x + v.y * v.y + v.z * v.z + v.w * v.w;
            sres += __shfl_xor_sync(0xffffffffu, sres, 8);
            sres += __shfl_xor_sync(0xffffffffu, sres, 4);
            sres += __shfl_xor_sync(0xffffffffu, sres, 2);
            sres += __shfl_xor_sync(0xffffffffu, sres, 1);
            if (ch4 == 0) s_y2[row] = sres;
        }
    }

    // ========== phase 1b: class prep (quad of lanes per class) ====================
    {
        const int cl = tid >> 2;                 // local class 0..63
        const int sq = tid & 3;                  // quad lane: d in [sq*16, sq*16+16)
        const int cc = cBase + cl;
        const bool valid = (cc < C);

        float P[16], A[16];
        if (valid) {
            const float4* pb4 = (const float4*)(p_vals + (size_t)cc * DDIM + sq * 16);
            const float4* ab4 = (const float4*)(a_vals + (size_t)cc * DDIM + sq * 16);
#pragma unroll
            for (int i = 0; i < 4; ++i) {
                float4 pv = pb4[i], av = ab4[i];
                P[i*4+0]=pv.x; P[i*4+1]=pv.y; P[i*4+2]=pv.z; P[i*4+3]=pv.w;
                A[i*4+0]=av.x; A[i*4+1]=av.y; A[i*4+2]=av.z; A[i*4+3]=av.w;
            }
        } else {
#pragma unroll
            for (int i = 0; i < 16; ++i) { P[i] = 0.f; A[i] = 0.f; }
        }

        float psq = 0.f;
#pragma unroll
        for (int i = 0; i < 16; ++i) psq += P[i] * P[i];
        psq += __shfl_xor_sync(0xffffffffu, psq, 1);
        psq += __shfl_xor_sync(0xffffffffu, psq, 2);

        float pn  = fmaxf(sqrtf(psq), 1e-15f);
        float arg = SQRT_K * pn;
        float t   = tanhf(arg) / arg;            // exp0 factor
        float p2  = t * t * psq;                 // |p_poin|^2
        float fac = 1.f + K_CURV * p2;

        float a2 = 0.f, pad = 0.f;
#pragma unroll
        for (int i = 0; i < 16; ++i) {
            float pp = t * P[i];
            float ap = fac * A[i];
            P[i] = pp; A[i] = ap;
            a2  += ap * ap;
            pad += pp * ap;
        }
        a2  += __shfl_xor_sync(0xffffffffu, a2, 1);
        a2  += __shfl_xor_sync(0xffffffffu, a2, 2);
        pad += __shfl_xor_sync(0xffffffffu, pad, 1);
        pad += __shfl_xor_sync(0xffffffffu, pad, 2);

        if (sq == 0) {
            float an  = fmaxf(sqrtf(a2), 1e-15f);
            float lam = 2.f / (1.f - K_CURV * p2);
            s_x2[cl] = p2;
            s_pa[cl] = -pad;                     // dot(mp, a_poin)
            s_sc[cl] = lam * an / SQRT_K;        // scale
            s_cf[cl] = 2.f * SQRT_K / an;        // folded consts
        }
        // interleaved (p,a) pairs, chunk-XOR swizzled by (c>>2)
        const int scl = (cl >> 2) & 15;
        float* base = pa + cl * 128;
#pragma unroll
        for (int mm = 0; mm < 8; ++mm) {
            int m = (sq * 8 + mm) ^ scl;
            *(float4*)(base + m * 4) =
                make_float4(P[2*mm], A[2*mm], P[2*mm+1], A[2*mm+1]);
        }
    }
    __syncthreads();

    // ========== phase 2: fused dual GEMM, 4b x 4c, pair = (p,a) ===================
    const int tx = tid & 15;                     // c0 = 4*tx
    const int ty = tid >> 4;                     // b0 = 4*ty
    const int b0 = ty * 4;
    const int c0 = tx * 4;
    const int cx4 = ((tx ^ ty) & 15) * 4;        // float-offset XOR for x side
    const float* xrow = xs + b0 * 128;
    const float* crow = pa + c0 * 128;

    ull acc[4][4];                               // [i=b][j=c] = (dotp, dota)
#pragma unroll
    for (int i = 0; i < 4; ++i)
#pragma unroll
        for (int j = 0; j < 4; ++j) acc[i][j] = 0ull;

#pragma unroll
    for (int t = 0; t < 32; ++t) {               // t = physical class chunk (2 d's)
        const int xo = (t * 4) ^ cx4;            // physical x chunk offset (floats)
        ulonglong2 xq[4], cq[4];
#pragma unroll
        for (int i = 0; i < 4; ++i)
            xq[i] = *(const ulonglong2*)(xrow + i * 128 + xo);
#pragma unroll
        for (int j = 0; j < 4; ++j)
            cq[j] = *(const ulonglong2*)(crow + j * 128 + t * 4);
#pragma unroll
        for (int j = 0; j < 4; ++j)
#pragma unroll
            for (int i = 0; i < 4; ++i) ffma2(acc[i][j], xq[i].x, cq[j].x);
#pragma unroll
        for (int j = 0; j < 4; ++j)
#pragma unroll
            for (int i = 0; i < 4; ++i) ffma2(acc[i][j], xq[i].y, cq[j].y);
    }

    // ========== phase 3: epilogue =================================================
    const int cg = cBase + c0;
    const bool wr = (cg + 3) < C;                // C % 4 == 0: all-in or all-out
#pragma unroll
    for (int i = 0; i < 4; ++i) {
        const float y2 = s_y2[b0 + i];
        float4 r;
        float* rp = (float*)&r;
#pragma unroll
        for (int j = 0; j < 4; ++j) {
            float2 d2 = unpack2(acc[i][j]);      // (dot(p,x), dot(a,x))
            float x2  = s_x2[c0 + j];
            float paj = s_pa[c0 + j];
            float xy  = -d2.x;                   // dot(mp, x)
            float Bf  = 1.f - K_CURV * x2;
            float base = fmaf(2.f * K_CURV, xy, 1.f);
            float Af   = fmaf(K_CURV, y2, base);
            float den  = fmaf((K_CURV * K_CURV) * x2, y2, base);
            float dotnum = fmaf(Af, paj, Bf * d2.y);
            float num  = fmaf(Af, fmaf(Af, x2, 2.f * Bf * xy), Bf * Bf * y2);
            float w    = fmaf(den, den, -K_CURV * num);
            float ratio = s_cf[c0 + j] * dotnum * den * rcp_a(w);
            float tt = fabsf(ratio);
            float z  = lg2_a(tt + sqrt_a(fmaf(tt, tt, 1.f))) * 0.69314718056f;
            rp[j] = s_sc[c0 + j] * copysignf(z, ratio);
        }
        if (wr) {
            const int bg = bBase + b0 + i;
            *(float4*)(out + (size_t)bg * C + cg) = r;
        }
    }
}

// ===================== launch ==================================================
extern "C" void kernel_launch(void* const* d_in, const int* in_sizes, int n_in,
                              void* d_out, int out_size) {
    const float* x = (const float*)d_in[0];
    const float* a = (const float*)d_in[1];
    const float* p = (const float*)d_in[2];
    float* out = (float*)d_out;
    const int B = in_sizes[0] / DDIM;   // 2048
    const int C = in_sizes[1] / DDIM;   // 1000

    cudaFuncSetAttribute(hmlr_fused, cudaFuncAttributeMaxDynamicSharedMemorySize, SM_TOTAL);
    dim3 grid((C + 63) / 64, B / 64);   // 16 x 32 = 512 blocks, 3/SM
    hmlr_fused<<<grid, 256, SM_TOTAL>>>(x, a, p, out, B, C);
}

// round 11
// speedup vs baseline: 3.1981x; 3.1981x over previous
#include <cuda_runtime.h>
#include <math.h>

// HyperbolicMLR fused. f32x2 pair = (p,a): one FFMA2 feeds both GEMMs.
// Chunk-major smem layouts with bank-group-complete XOR swizzles (see analysis).
// Block 64b x 64c, thread 4b x 4c, 256 thr, 3 blocks/SM.

#define K_CURV 0.1f
#define SQRT_K 0.31622776601683794f
#define DDIM   64

typedef unsigned long long ull;

// float offsets in dynamic smem
#define SMF_XS   0        // x dup pairs, chunk-major: 32 chunks * 256 floats
#define SMF_PA   8192     // (p,a) pairs, chunk-major: 32 chunks * 256 floats
#define SMF_X2   16384    // |p_poin|^2      [64]
#define SMF_PAC  16448    // dot(mp,a_poin)  [64]
#define SMF_SC   16512    // scale           [64]
#define SMF_CF   16576    // 2*sqrt_k/a_norm [64]
#define SMF_Y2   16640    // |x_b|^2         [64]
#define SM_TOTAL (16704 * 4)

__device__ __forceinline__ float2 unpack2(ull v) {
    float2 r;
    asm("mov.b64 {%0, %1}, %2;" : "=f"(r.x), "=f"(r.y) : "l"(v));
    return r;
}
__device__ __forceinline__ void ffma2(ull& acc, ull a, ull b) {
    asm("fma.rn.f32x2 %0, %1, %2, %0;" : "+l"(acc) : "l"(a), "l"(b));
}
__device__ __forceinline__ float rcp_a(float x)  { float r; asm("rcp.approx.f32 %0, %1;"  : "=f"(r) : "f"(x)); return r; }
__device__ __forceinline__ float sqrt_a(float x) { float r; asm("sqrt.approx.f32 %0, %1;" : "=f"(r) : "f"(x)); return r; }
__device__ __forceinline__ float lg2_a(float x)  { float r; asm("lg2.approx.f32 %0, %1;"  : "=f"(r) : "f"(x)); return r; }

__global__ void __launch_bounds__(256, 3)
hmlr_fused(const float* __restrict__ x,
           const float* __restrict__ a_vals,
           const float* __restrict__ p_vals,
           float* __restrict__ out, int B, int C) {
    extern __shared__ __align__(16) float sm[];
    float* xs   = sm + SMF_XS;
    float* pa   = sm + SMF_PA;
    float* s_x2 = sm + SMF_X2;
    float* s_pa = sm + SMF_PAC;
    float* s_sc = sm + SMF_SC;
    float* s_cf = sm + SMF_CF;
    float* s_y2 = sm + SMF_Y2;

    const int tid   = threadIdx.x;
    const int cBase = blockIdx.x * 64;
    const int bBase = blockIdx.y * 64;

    // ===== phase 1a: x tile (dup pairs, chunk-major, g = r ^ (m&7)) + y2 =======
    // warp covers one full row per iteration: r fixed, m = lane 0..31.
    {
        const float2* Xv = (const float2*)(x + (size_t)bBase * DDIM);
#pragma unroll
        for (int it = 0; it < 8; ++it) {
            int lin = tid + it * 256;
            int r = lin >> 5;                    // b row 0..63 (fixed per warp)
            int m = lin & 31;                    // chunk = lane (d = 2m, 2m+1)
            float2 v = Xv[lin];
            int g = r ^ (m & 7);                 // bank-group-complete swizzle
            *(float4*)(xs + m * 256 + g * 4) = make_float4(v.x, v.x, v.y, v.y);
            float s = v.x * v.x + v.y * v.y;
            s += __shfl_xor_sync(0xffffffffu, s, 16);
            s += __shfl_xor_sync(0xffffffffu, s, 8);
            s += __shfl_xor_sync(0xffffffffu, s, 4);
            s += __shfl_xor_sync(0xffffffffu, s, 2);
            s += __shfl_xor_sync(0xffffffffu, s, 1);
            if (m == 0) s_y2[r] = s;
        }
    }

    // ===== phase 1b: class prep (quad of lanes per class) ======================
    {
        const int cl = tid >> 2;                 // local class 0..63
        const int sq = tid & 3;                  // quad lane: d in [sq*16, sq*16+16)
        const int cc = cBase + cl;
        const bool valid = (cc < C);

        float P[16], A[16];
        if (valid) {
            const float4* pb4 = (const float4*)(p_vals + (size_t)cc * DDIM + sq * 16);
            const float4* ab4 = (const float4*)(a_vals + (size_t)cc * DDIM + sq * 16);
#pragma unroll
            for (int i = 0; i < 4; ++i) {
                float4 pv = pb4[i], av = ab4[i];
                P[i*4+0]=pv.x; P[i*4+1]=pv.y; P[i*4+2]=pv.z; P[i*4+3]=pv.w;
                A[i*4+0]=av.x; A[i*4+1]=av.y; A[i*4+2]=av.z; A[i*4+3]=av.w;
            }
        } else {
#pragma unroll
            for (int i = 0; i < 16; ++i) { P[i] = 0.f; A[i] = 0.f; }
        }

        float psq = 0.f;
#pragma unroll
        for (int i = 0; i < 16; ++i) psq += P[i] * P[i];
        psq += __shfl_xor_sync(0xffffffffu, psq, 1);
        psq += __shfl_xor_sync(0xffffffffu, psq, 2);

        float pn  = fmaxf(sqrtf(psq), 1e-15f);
        float arg = SQRT_K * pn;
        float t   = tanhf(arg) / arg;            // exp0 factor
        float p2  = t * t * psq;                 // |p_poin|^2
        float fac = 1.f + K_CURV * p2;

        float a2 = 0.f, pad = 0.f;
#pragma unroll
        for (int i = 0; i < 16; ++i) {
            float pp = t * P[i];
            float ap = fac * A[i];
            P[i] = pp; A[i] = ap;
            a2  += ap * ap;
            pad += pp * ap;
        }
        a2  += __shfl_xor_sync(0xffffffffu, a2, 1);
        a2  += __shfl_xor_sync(0xffffffffu, a2, 2);
        pad += __shfl_xor_sync(0xffffffffu, pad, 1);
        pad += __shfl_xor_sync(0xffffffffu, pad, 2);

        if (sq == 0) {
            float an  = fmaxf(sqrtf(a2), 1e-15f);
            float lam = 2.f / (1.f - K_CURV * p2);
            s_x2[cl] = p2;
            s_pa[cl] = -pad;                     // dot(mp, a_poin)
            s_sc[cl] = lam * an / SQRT_K;        // scale
            s_cf[cl] = 2.f * SQRT_K / an;        // folded consts
        }
        // chunk-major store: granule = (cl>>2 ^ 2*(m>>3)) + (cl&3)*16, m>>3 == sq
        float* base = pa + (((cl >> 2) ^ (sq << 1)) + (cl & 3) * 16) * 4;
#pragma unroll
        for (int mm = 0; mm < 8; ++mm) {
            int m = sq * 8 + mm;                 // chunk: d = 16*sq + 2*mm (+1)
            *(float4*)(base + m * 256) =
                make_float4(P[2*mm], A[2*mm], P[2*mm+1], A[2*mm+1]);
        }
    }
    __syncthreads();

    // ===== phase 2: fused dual GEMM, 4b x 4c, zero address-ALU =================
    const int tx = tid & 15;                     // c0 = 4*tx
    const int ty = tid >> 4;                     // b0 = 4*ty
    const int b0 = ty * 4;
    const int c0 = tx * 4;

    // x bases: granule (ty*4) ^ (t&4) -> two pointers, select by t bit 2
    const float* xbA = xs + (b0)       * 4;
    const float* xbB = xs + (b0 ^ 4)   * 4;
    // class bases: granule (tx ^ 2*(t>>3)) -> four pointers, select by t>>3
    const float* cb0 = pa + (tx)       * 4;
    const float* cb1 = pa + (tx ^ 2)   * 4;
    const float* cb2 = pa + (tx ^ 4)   * 4;
    const float* cb3 = pa + (tx ^ 6)   * 4;

    ull acc[4][4];                               // [i=b][j=c] = (dotp, dota)
#pragma unroll
    for (int i = 0; i < 4; ++i)
#pragma unroll
        for (int j = 0; j < 4; ++j) acc[i][j] = 0ull;

#pragma unroll
    for (int t = 0; t < 32; ++t) {               // chunk t covers d = 2t, 2t+1
        const float* xbase = (t & 4) ? xbB : xbA;
        const float* cbase = (t >> 3 == 0) ? cb0 : (t >> 3 == 1) ? cb1
                           : (t >> 3 == 2) ? cb2 : cb3;
        ulonglong2 xq[4], cq[4];
#pragma unroll
        for (int k = 0; k < 4; ++k)              // row perm: granule k holds b0 + (k^(t&3))
            xq[k ^ (t & 3)] = *(const ulonglong2*)(xbase + t * 256 + k * 4);
#pragma unroll
        for (int j = 0; j < 4; ++j)
            cq[j] = *(const ulonglong2*)(cbase + t * 256 + j * 64);
#pragma unroll
        for (int j = 0; j < 4; ++j)
#pragma unroll
            for (int i = 0; i < 4; ++i) ffma2(acc[i][j], xq[i].x, cq[j].x);
#pragma unroll
        for (int j = 0; j < 4; ++j)
#pragma unroll
            for (int i = 0; i < 4; ++i) ffma2(acc[i][j], xq[i].y, cq[j].y);
    }

    // ===== phase 3: epilogue ====================================================
    const int cg = cBase + c0;
    const bool wr = (cg + 3) < C;                // C % 4 == 0: all-in or all-out
#pragma unroll
    for (int i = 0; i < 4; ++i) {
        const float y2 = s_y2[b0 + i];
        float4 r;
        float* rp = (float*)&r;
#pragma unroll
        for (int j = 0; j < 4; ++j) {
            float2 d2 = unpack2(acc[i][j]);      // (dot(p,x), dot(a,x))
            float x2  = s_x2[c0 + j];
            float paj = s_pa[c0 + j];
            float xy  = -d2.x;                   // dot(mp, x)
            float Bf  = 1.f - K_CURV * x2;
            float base = fmaf(2.f * K_CURV, xy, 1.f);
            float Af   = fmaf(K_CURV, y2, base);
            float den  = fmaf((K_CURV * K_CURV) * x2, y2, base);
            float dotnum = fmaf(Af, paj, Bf * d2.y);
            float num  = fmaf(Af, fmaf(Af, x2, 2.f * Bf * xy), Bf * Bf * y2);
            float w    = fmaf(den, den, -K_CURV * num);
            float ratio = s_cf[c0 + j] * dotnum * den * rcp_a(w);
            float tt = fabsf(ratio);
            float z  = lg2_a(tt + sqrt_a(fmaf(tt, tt, 1.f))) * 0.69314718056f;
            rp[j] = s_sc[c0 + j] * copysignf(z, ratio);
        }
        if (wr) {
            const int bg = bBase + b0 + i;
            *(float4*)(out + (size_t)bg * C + cg) = r;
        }
    }
}

// ===================== launch ==================================================
extern "C" void kernel_launch(void* const* d_in, const int* in_sizes, int n_in,
                              void* d_out, int out_size) {
    const float* x = (const float*)d_in[0];
    const float* a = (const float*)d_in[1];
    const float* p = (const float*)d_in[2];
    float* out = (float*)d_out;
    const int B = in_sizes[0] / DDIM;   // 2048
    const int C = in_sizes[1] / DDIM;   // 1000

    cudaFuncSetAttribute(hmlr_fused, cudaFuncAttributeMaxDynamicSharedMemorySize, SM_TOTAL);
    dim3 grid((C + 63) / 64, B / 64);   // 16 x 32 = 512 blocks, 3/SM
    hmlr_fused<<<grid, 256, SM_TOTAL>>>(x, a, p, out, B, C);
}